// round 16
// baseline (speedup 1.0000x reference)
#include <cuda_runtime.h>
#include <stdint.h>
#include <math.h>

#define BB 16
#define CC 3
#define HW 50176             // 224*224
#define EMBN 16
#define NSEG 196
#define MCN 16
#define NTOT (BB*NSEG*MCN)   // 50176
#define NPB (NSEG*MCN)       // 3136 rng elems per batch
#define RR 15
#define NPK 120
#define BLKA 7
#define NSNAP (NSEG/BLKA)    // 28
#define LSTR 121             // shared snapshot stride (coprime with 32)
#define CH 14
#define NCH (NSEG/CH)        // 14
#define NQC 32               // conv CTAs per batch
#define NREP 8               // accumulator replicas
#define NRNGB 13             // rng CTAs per batch
#define NCONV (BB*NQC)       // 512
#define CID0 NCONV           // 512
#define LID0 (NCONV + BB*NRNGB)  // 720
#define MID0 (LID0 + BB)     // 736
#define NMASK (HW*4/256)     // 784 mask CTAs per batch
#define NCONS (NMASK + 4)    // + 4 sigma CTAs

#define SZ_MASK (BB*CC*HW*MCN)
#define OFF_GP  (SZ_MASK)
#define OFF_PP  (OFF_GP + BB*NSEG)
#define OFF_SIG (OFF_PP + BB*HW)

// ---- device state (zero-init at load; protocol restores zeros each launch) ----
__device__ float4 g_acc[NREP*BB*NSEG];
__device__ float g_gemb[BB*NSEG*16];
__device__ float g_eps[NTOT];
__device__ float g_logi[NTOT];
__device__ float g_hard[NTOT];
__device__ int g_convdone[BB];
__device__ int g_rngdone[BB];
__device__ int g_flag[BB];
__device__ int g_done[BB];

// -------------------- threefry2x32 --------------------
__host__ __device__ inline void tf2x32(uint32_t k0, uint32_t k1,
                                       uint32_t x0, uint32_t x1,
                                       uint32_t& o0, uint32_t& o1) {
    uint32_t ks2 = k0 ^ k1 ^ 0x1BD11BDAu;
    x0 += k0; x1 += k1;
#define TF_RND(r) { x0 += x1; x1 = (x1 << (r)) | (x1 >> (32 - (r))); x1 ^= x0; }
    TF_RND(13) TF_RND(15) TF_RND(26) TF_RND(6)
    x0 += k1;  x1 += ks2 + 1u;
    TF_RND(17) TF_RND(29) TF_RND(16) TF_RND(24)
    x0 += ks2; x1 += k0 + 2u;
    TF_RND(13) TF_RND(15) TF_RND(26) TF_RND(6)
    x0 += k0;  x1 += k1 + 3u;
    TF_RND(17) TF_RND(29) TF_RND(16) TF_RND(24)
    x0 += k1;  x1 += ks2 + 4u;
    TF_RND(13) TF_RND(15) TF_RND(26) TF_RND(6)
    x0 += ks2; x1 += k0 + 5u;
#undef TF_RND
    o0 = x0; o1 = x1;
}

__device__ __forceinline__ float erfinv_xla(float x) {
    float w = -log1pf(-x * x);
    float p;
    if (w < 5.0f) {
        w = w - 2.5f;
        p =               2.81022636e-08f;
        p = fmaf(p, w,    3.43273939e-07f);
        p = fmaf(p, w,   -3.5233877e-06f);
        p = fmaf(p, w,   -4.39150654e-06f);
        p = fmaf(p, w,    0.00021858087f);
        p = fmaf(p, w,   -0.00125372503f);
        p = fmaf(p, w,   -0.00417768164f);
        p = fmaf(p, w,    0.246640727f);
        p = fmaf(p, w,    1.50140941f);
    } else {
        w = sqrtf(w) - 3.0f;
        p =              -0.000200214257f;
        p = fmaf(p, w,    0.000100950558f);
        p = fmaf(p, w,    0.00134934322f);
        p = fmaf(p, w,   -0.00367342844f);
        p = fmaf(p, w,    0.00573950773f);
        p = fmaf(p, w,   -0.0076224613f);
        p = fmaf(p, w,    0.00943887047f);
        p = fmaf(p, w,    1.00167406f);
        p = fmaf(p, w,    2.83297682f);
    }
    return p * x;
}

// ==================== single fused kernel ====================
__global__ __launch_bounds__(256, 3) void k_all(
        const float* __restrict__ x, const int* __restrict__ groups,
        const float* __restrict__ Wc, const float* __restrict__ bc,
        float* __restrict__ out_mask, float* __restrict__ out_gp,
        float* __restrict__ out_pp, float* __restrict__ out_sig,
        uint32_t g0, uint32_t g1, uint32_t u0, uint32_t u1) {
    __shared__ float pool[11096];
    const int bid = blockIdx.x, tid = threadIdx.x;

    // ---------------- producers: conv + RED segment sums ----------------
    if (bid < NCONV) {
        const int b = bid / NQC;
        const int q = bid % NQC;
        const float w0 = Wc[0], w1 = Wc[1], w2 = Wc[2], b0 = bc[0];
        const float4* xb = (const float4*)(x + (size_t)b*CC*HW);
        const int4*   gb = (const int4*)(groups + (size_t)b*HW);
        float4* pp = (float4*)(out_pp + (size_t)b*HW);
        float4* acc = g_acc + ((q & (NREP-1))*BB + b)*NSEG;
        const int Q4 = HW/4/NQC;           // 392
        const int v0 = q * Q4;
        for (int v = v0 + tid; v < v0 + Q4; v += 256) {
            float4 X0 = xb[v], X1 = xb[HW/4 + v], X2 = xb[2*(HW/4) + v];
            int4 G = gb[v];
            float4 o;
            o.x = __fdividef(1.0f, 1.0f + __expf(-(fmaf(X2.x, w2, fmaf(X1.x, w1, X0.x*w0)) + b0)));
            o.y = __fdividef(1.0f, 1.0f + __expf(-(fmaf(X2.y, w2, fmaf(X1.y, w1, X0.y*w0)) + b0)));
            o.z = __fdividef(1.0f, 1.0f + __expf(-(fmaf(X2.z, w2, fmaf(X1.z, w1, X0.z*w0)) + b0)));
            o.w = __fdividef(1.0f, 1.0f + __expf(-(fmaf(X2.w, w2, fmaf(X1.w, w1, X0.w*w0)) + b0)));
            pp[v] = o;
            atomicAdd(&acc[G.x], make_float4(X0.x, X1.x, X2.x, 1.0f));
            atomicAdd(&acc[G.y], make_float4(X0.y, X1.y, X2.y, 1.0f));
            atomicAdd(&acc[G.z], make_float4(X0.z, X1.z, X2.z, 1.0f));
            atomicAdd(&acc[G.w], make_float4(X0.w, X1.w, X2.w, 1.0f));
        }
        __threadfence();
        __syncthreads();
        if (tid == 0) atomicAdd(&g_convdone[b], 1);
        return;
    }

    // ---------------- producers: RNG ----------------
    if (bid < LID0) {
        const int r = bid - CID0;
        const int b = r / NRNGB, sub = r % NRNGB;
        const int j = sub*256 + tid;
        if (j < NPB) {
            const int i = b*NPB + j;
            uint32_t a0, a1;
            tf2x32(g0, g1, 0u, (uint32_t)i, a0, a1);
            {
                uint32_t bits = a0 ^ a1;
                float f  = __uint_as_float((bits >> 9) | 0x3f800000u) - 1.0f;
                const float lo = __uint_as_float(0xBF7FFFFFu);
                const float d  = __fadd_rn(1.0f, -lo);
                float u  = fmaxf(lo, __fadd_rn(__fmul_rn(f, d), lo));
                g_eps[i] = __uint_as_float(0x3FB504F3u) * erfinv_xla(u);
            }
            tf2x32(u0, u1, 0u, (uint32_t)i, a0, a1);
            {
                uint32_t bits = a0 ^ a1;
                float f  = __uint_as_float((bits >> 9) | 0x3f800000u) - 1.0f;
                const float lo = 1e-6f;
                const float hi = (float)(1.0 - 1e-6);
                const float d  = __fadd_rn(hi, -lo);
                float u  = fmaxf(lo, __fadd_rn(__fmul_rn(f, d), lo));
                g_logi[i] = logf(u) - log1pf(-u);
            }
        }
        __threadfence();
        __syncthreads();
        if (tid == 0) atomicAdd(&g_rngdone[b], 1);
        return;
    }

    // ---------------- lr: means + low-rank Cholesky + logits + hard bits ----------------
    if (bid < MID0) {
        const int b = bid - LID0;
        const float s2 = 0.001f;
        const float inv_s2 = 1.0f / s2;
        float (*su)[17] = (float(*)[17])pool;            // 3332
        float (*sv)[17] = (float(*)[17])(pool + 3332);   // 3332
        float* sbuf = pool + 6664;                       // 3584
        float* ssd  = pool + 10248;
        float* sisd = ssd + 196;
        float* sden = sisd + 196;
        float* smu  = sden + 196;
        float* sW   = pool + 10248 + 784;                // 48
        float* sB   = sW + 48;                           // 16

        if (tid < EMBN*CC) sW[tid] = Wc[tid];
        if (tid >= 64 && tid < 64 + EMBN) sB[tid - 64] = bc[tid - 64];
        if (tid == 0) {
            while (((volatile int*)g_convdone)[b] != NQC ||
                   ((volatile int*)g_rngdone)[b] != NRNGB) __nanosleep(64);
            __threadfence();
        }
        __syncthreads();

        // means from replicated sums (linearity)
        if (tid < NSEG) {
            float4 s = make_float4(0.f, 0.f, 0.f, 0.f);
#pragma unroll
            for (int rp = 0; rp < NREP; ++rp) {
                float4 v = g_acc[(rp*BB + b)*NSEG + tid];
                s.x += v.x; s.y += v.y; s.z += v.z; s.w += v.w;
            }
            float cm = fmaxf(s.w, 1.0f);
            float mx0 = s.x/cm, mx1 = s.y/cm, mx2 = s.z/cm;
            float mu = fmaf(mx2, sW[2], fmaf(mx1, sW[1], mx0*sW[0])) + sB[0];
            smu[tid] = mu;
            out_gp[b*NSEG + tid] = __fdividef(1.0f, 1.0f + __expf(-mu));
            float* ge = g_gemb + (b*NSEG + tid)*16;
#pragma unroll
            for (int c = 0; c < RR; ++c) {
                int e = c + 1;
                float v = fmaf(mx2, sW[e*3+2], fmaf(mx1, sW[e*3+1], mx0*sW[e*3])) + sB[e];
                su[tid][c] = v; ge[c] = v;
            }
            ge[15] = 0.0f;
        }
        __syncthreads();
        // zero accumulators for next launch
        {
            float4 z = make_float4(0.f, 0.f, 0.f, 0.f);
            for (int i = tid; i < NREP*NSEG; i += 256)
                g_acc[((i / NSEG)*BB + b)*NSEG + (i % NSEG)] = z;
        }

        // snapshot prefix Grams (stride LSTR in sbuf)
        if (tid < NPK) {
            int e = tid, j = 0;
            while ((j+1)*(j+2)/2 <= e) ++j;
            int k = e - j*(j+1)/2;
            float accg = 0.0f;
            for (int blk = 0; blk < NSNAP; ++blk) {
                sbuf[blk*LSTR + e] = accg;
                int l0 = blk*BLKA;
#pragma unroll
                for (int l = 0; l < BLKA; ++l)
                    accg = fmaf(su[l0+l][j], su[l0+l][k], accg);
            }
        }
        __syncthreads();

        // in-shared packed Cholesky of M = I + G/s2 (28 threads)
        if (tid < NSNAP) {
            float* Ls = sbuf + tid*LSTR;
            int e = 0;
            for (int j = 0; j < RR; ++j)
                for (int k = 0; k <= j; ++k, ++e)
                    Ls[e] = (j == k) ? fmaf(Ls[e], inv_s2, 1.0f) : Ls[e]*inv_s2;
            for (int k = 0; k < RR; ++k) {
                float dk = sqrtf(Ls[k*(k+1)/2 + k]);
                Ls[k*(k+1)/2 + k] = dk;
                float inv = 1.0f / dk;
                for (int j = k+1; j < RR; ++j) Ls[j*(j+1)/2 + k] *= inv;
                for (int j = k+1; j < RR; ++j) {
                    float ljk = Ls[j*(j+1)/2 + k];
                    for (int l = k+1; l <= j; ++l)
                        Ls[j*(j+1)/2 + l] = fmaf(-ljk, Ls[l*(l+1)/2 + k], Ls[j*(j+1)/2 + l]);
                }
            }
        }
        __syncthreads();

        // triangular solves against broadcast snapshot factor
        float t[RR];
        int base = 0;
        if (tid < NSEG) {
            int blk = tid / BLKA; base = blk * BLKA;
            const float* Lb = sbuf + blk*LSTR;
            float y[RR];
#pragma unroll
            for (int j = 0; j < RR; ++j) {
                float s = su[tid][j];
#pragma unroll
                for (int k = 0; k < j; ++k) s = fmaf(-Lb[j*(j+1)/2 + k], y[k], s);
                y[j] = s / Lb[j*(j+1)/2 + j];
            }
#pragma unroll
            for (int j = RR-1; j >= 0; --j) {
                float s = y[j];
#pragma unroll
                for (int k = j+1; k < RR; ++k) s = fmaf(-Lb[k*(k+1)/2 + j], t[k], s);
                t[j] = s / Lb[j*(j+1)/2 + j];
            }
        }
        if (tid < NSEG && tid == base) {
            float d = s2;
#pragma unroll
            for (int k = 0; k < RR; ++k) { d = fmaf(su[tid][k], t[k], d); sv[tid][k] = t[k]; }
            sden[tid] = d;
        }
        for (int r = 1; r < BLKA; ++r) {
            __syncthreads();
            if (tid < NSEG) {
                int off = tid - base;
                if (off >= r) {
                    int l = base + r - 1;
                    float cdot = 0.0f;
#pragma unroll
                    for (int k = 0; k < RR; ++k) cdot = fmaf(sv[l][k], su[tid][k], cdot);
                    float scale = cdot / sden[l];
#pragma unroll
                    for (int k = 0; k < RR; ++k) t[k] = fmaf(-scale, sv[l][k], t[k]);
                }
                if (off == r) {
                    float d = s2;
#pragma unroll
                    for (int k = 0; k < RR; ++k) { d = fmaf(su[tid][k], t[k], d); sv[tid][k] = t[k]; }
                    sden[tid] = d;
                }
            }
        }
        __syncthreads();
        if (tid < NSEG) {
            float sd = sqrtf(sden[tid]);
            ssd[tid] = sd;
            sisd[tid] = 1.0f / sd;
        }
        __syncthreads();   // phase A done; sbuf reused below

        // phase B: chunked scan
        const int m = tid & 15, c = tid >> 4;
        if (c < NCH) {
            float T[RR];
#pragma unroll
            for (int k = 0; k < RR; ++k) T[k] = 0.0f;
            for (int r = 0; r < CH; ++r) {
                int j = c*CH + r;
                float w = g_eps[(b*NSEG + j)*MCN + m] * sisd[j];
#pragma unroll
                for (int k = 0; k < RR; ++k) T[k] = fmaf(w, sv[j][k], T[k]);
            }
            float* Tout = sbuf + (c*MCN + m)*16;
#pragma unroll
            for (int k = 0; k < RR; ++k) Tout[k] = T[k];
        }
        __syncthreads();
        if (c < NCH) {
            float S[RR];
#pragma unroll
            for (int k = 0; k < RR; ++k) S[k] = 0.0f;
            for (int c2 = 0; c2 < c; ++c2) {
                const float* Tc = sbuf + (c2*MCN + m)*16;
#pragma unroll
                for (int k = 0; k < RR; ++k) S[k] += Tc[k];
            }
            for (int r = 0; r < CH; ++r) {
                int j = c*CH + r;
                int gi = (b*NSEG + j)*MCN + m;
                float ej = g_eps[gi];
                float dot = 0.0f;
#pragma unroll
                for (int k = 0; k < RR; ++k) dot = fmaf(su[j][k], S[k], dot);
                float z = smu[j] + dot + ssd[j]*ej + g_logi[gi];
                g_hard[gi] = (z > 0.0f) ? 1.0f : 0.0f;
                float w = ej * sisd[j];
#pragma unroll
                for (int k = 0; k < RR; ++k) S[k] = fmaf(w, sv[j][k], S[k]);
            }
        }
        __threadfence();
        __syncthreads();
        if (tid == 0) {
            g_convdone[b] = 0;
            g_rngdone[b] = 0;
            __threadfence();
            atomicExch(&g_flag[b], 1);
        }
        return;
    }

    // ---------------- consumers: mask gather + sigma ----------------
    {
        const int r = bid - MID0;
        const int b = r / NCONS;
        const int s = r - b*NCONS;
        if (tid == 0) {
            while (((volatile int*)g_flag)[b] == 0) __nanosleep(64);
            __threadfence();
        }
        __syncthreads();

        if (s < NMASK) {
            const int idx = s*256 + tid;
            const int p = idx >> 2, j = idx & 3;
            const int g = __ldg(&groups[b*HW + p]);
            float4 v = ((const float4*)g_hard)[(b*NSEG + g)*4 + j];
#pragma unroll
            for (int c = 0; c < CC; ++c)
                __stcs(((float4*)out_mask) + ((size_t)(b*CC + c)*HW + p)*4 + j, v);
        } else {
            float (*sgm)[17] = (float(*)[17])pool;
            const int q = s - NMASK;
            for (int ii = tid; ii < NSEG*16; ii += 256)
                sgm[ii >> 4][ii & 15] = g_gemb[(size_t)b*NSEG*16 + ii];
            __syncthreads();
            const int r0 = q * 49;
            for (int e = tid; e < 49*NSEG; e += 256) {
                int row = r0 + e / NSEG;
                int col = e - (e / NSEG) * NSEG;
                float d = 0.0f;
#pragma unroll
                for (int k = 0; k < RR; ++k) d = fmaf(sgm[row][k], sgm[col][k], d);
                if (row == col) d += 0.001f;
                out_sig[((size_t)b*NSEG + row)*NSEG + col] = d;
            }
        }
        __syncthreads();
        if (tid == 0) {
            int d = atomicAdd(&g_done[b], 1);
            if (d == NCONS - 1) { g_done[b] = 0; g_flag[b] = 0; }
        }
    }
}

// -------------------- launch --------------------
extern "C" void kernel_launch(void* const* d_in, const int* in_sizes, int n_in,
                              void* d_out, int out_size) {
    (void)in_sizes; (void)n_in; (void)out_size;
    const float* x      = (const float*)d_in[0];
    const int*   groups = (const int*)d_in[1];
    const float* Wc     = (const float*)d_in[2];
    const float* bc     = (const float*)d_in[3];
    float* out      = (float*)d_out;

    uint32_t kg0, kg1, ku0, ku1;
    tf2x32(0u, 42u, 0u, 0u, kg0, kg1);
    tf2x32(0u, 42u, 0u, 1u, ku0, ku1);

    const int grid = MID0 + BB*NCONS;   // 736 + 12608 = 13344
    k_all<<<grid, 256>>>(x, groups, Wc, bc,
                         out, out + OFF_GP, out + OFF_PP, out + OFF_SIG,
                         kg0, kg1, ku0, ku1);
}